// round 5
// baseline (speedup 1.0000x reference)
#include <cuda_runtime.h>
#include <cuda_bf16.h>

// ---------------------------------------------------------------------------
// 2-layer GCN, pull aggregation via on-device CSR, GEMMs on tf32 tensor cores.
// ---------------------------------------------------------------------------

#define NMAX   50048
#define EMAX   800000
#define INF    128
#define OUTF   64

__device__ int   g_is64;
__device__ int   g_src [EMAX];
__device__ int   g_dst [EMAX];
__device__ int   g_cnt [NMAX];        // in-degree (without self loop)
__device__ int   g_ptr [NMAX + 1];    // CSR row pointers
__device__ int   g_fill[NMAX];        // fill cursors
__device__ int2  g_edge[EMAX];        // packed (src, __float_as_int(coeff))
__device__ float g_dinv[NMAX];
__device__ float g_h1  [NMAX * INF];  // X @ W1
__device__ float g_agg1[NMAX * INF];  // aggregated layer-1 (pre bias/relu)
__device__ float g_h2  [NMAX * OUTF]; // relu(agg1+b1) @ W2

// ---------------------------------------------------------------------------
__global__ void k_probe(const int* __restrict__ w32, int words) {
    __shared__ int viol;
    if (threadIdx.x == 0) viol = 0;
    __syncthreads();
    int nchk = words / 2;
    if (nchk > 32768) nchk = 32768;
    int bad = 0;
    for (int i = threadIdx.x; i < nchk; i += blockDim.x)
        if (w32[2 * i + 1] != 0) bad = 1;
    if (bad) atomicOr(&viol, 1);
    __syncthreads();
    if (threadIdx.x == 0) g_is64 = (viol == 0) ? 1 : 0;
}

__global__ void k_zero_cnt(int n) {
    int i = blockIdx.x * blockDim.x + threadIdx.x;
    if (i < n) g_cnt[i] = 0;
}

__global__ void k_decode_count(const void* __restrict__ ei, int E) {
    int e = blockIdx.x * blockDim.x + threadIdx.x;
    if (e >= E) return;
    int s, d;
    if (g_is64) {
        const long long* p = (const long long*)ei;
        s = (int)p[e];  d = (int)p[E + e];
    } else {
        const int* p = (const int*)ei;
        s = p[e];       d = p[E + e];
    }
    g_src[e] = s;
    g_dst[e] = d;
    atomicAdd(&g_cnt[d], 1);
}

// single-block scan of g_cnt -> g_ptr/g_fill, plus dinv computation (fused)
__global__ void k_scan(int n) {
    __shared__ int ssum[1024];
    const int tid   = threadIdx.x;
    const int chunk = (n + 1023) / 1024;
    const int lo    = tid * chunk;
    const int hi    = min(lo + chunk, n);
    int s = 0;
    for (int i = lo; i < hi; i++) {
        int c = g_cnt[i];
        s += c;
        g_dinv[i] = rsqrtf((float)(c + 1));   // +1 self loop
    }
    ssum[tid] = s;
    __syncthreads();
    int v = s;
    for (int off = 1; off < 1024; off <<= 1) {
        int t = (tid >= off) ? ssum[tid - off] : 0;
        __syncthreads();
        ssum[tid] += t;
        __syncthreads();
    }
    int run = ssum[tid] - v;
    for (int i = lo; i < hi; i++) {
        int c = g_cnt[i];
        g_ptr[i]  = run;
        g_fill[i] = run;
        run += c;
    }
    if (hi == n && lo <= n) g_ptr[n] = run;
}

__global__ void k_fillcsr(int E) {
    int e = blockIdx.x * blockDim.x + threadIdx.x;
    if (e >= E) return;
    int s = g_src[e];
    int d = g_dst[e];
    float c = g_dinv[s] * g_dinv[d];
    int pos = atomicAdd(&g_fill[d], 1);
    g_edge[pos] = make_int2(s, __float_as_int(c));
}

// ---------------------------------------------------------------------------
// tf32 tensor-core GEMM:  Y[M,TN] = op(X)[M,128] * W[128,TN]
// 128 threads / 4 warps; warp owns 16 rows x TN cols; mma.m16n8k8 tf32.
// PRELU: X = max(g_agg1 + bias, 0), Y = g_h2;  else X = param, Y = g_h1.
// ---------------------------------------------------------------------------
__device__ __forceinline__ unsigned f2tf(float f) {
    unsigned r;
    asm("cvt.rna.tf32.f32 %0, %1;" : "=r"(r) : "f"(f));
    return r;
}

template <int TN, bool PRELU>
__global__ void k_gemm_tf32(const float* __restrict__ Xin, const float* __restrict__ W,
                            const float* __restrict__ bias_in, int M)
{
    constexpr int KC  = 32;         // k-chunk
    constexpr int NT  = TN / 8;     // n-tiles per warp
    constexpr int PAD = 36;         // smem row stride (floats): (4r+k)%32 conflict-free

    const float* __restrict__ X = PRELU ? (const float*)g_agg1 : Xin;
    float* __restrict__ Y       = PRELU ? g_h2 : g_h1;

    __shared__ unsigned xs[64 * PAD];   // X tile 64 x KC (tf32), stride PAD
    __shared__ unsigned wt[TN * PAD];   // W chunk transposed [n][k], stride PAD

    const int tid  = threadIdx.x;
    const int lane = tid & 31;
    const int wid  = tid >> 5;
    const int m0   = blockIdx.x * 64;
    const int mw   = wid * 16;          // warp's row base within tile

    float acc[NT][4];
#pragma unroll
    for (int t = 0; t < NT; t++) { acc[t][0]=acc[t][1]=acc[t][2]=acc[t][3]=0.f; }

    const int r4 = lane >> 2;           // 0..7
    const int c4 = lane & 3;            // 0..3

    for (int kc = 0; kc < 128; kc += KC) {
        // --- X tile: 64 rows x KC floats = 512 float4, 128 threads x 4 ---
#pragma unroll
        for (int i = 0; i < 4; i++) {
            int idx = tid + i * 128;          // 0..511
            int r   = idx >> 3;               // row 0..63
            int kv  = (idx & 7) * 4;          // k offset
            int row = m0 + r;
            float4 v = make_float4(0.f, 0.f, 0.f, 0.f);
            if (row < M) v = *(const float4*)&X[row * 128 + kc + kv];
            if (PRELU) {
                float4 b = *(const float4*)&bias_in[kc + kv];
                v.x = fmaxf(v.x + b.x, 0.f);
                v.y = fmaxf(v.y + b.y, 0.f);
                v.z = fmaxf(v.z + b.z, 0.f);
                v.w = fmaxf(v.w + b.w, 0.f);
            }
            uint4 u = make_uint4(f2tf(v.x), f2tf(v.y), f2tf(v.z), f2tf(v.w));
            *(uint4*)&xs[r * PAD + kv] = u;   // PAD%4==0 -> 16B aligned
        }
        // --- W chunk transposed: read [kk][n] float4, write wt[n][kk] ---
#pragma unroll
        for (int i = 0; i < (KC * TN / 4) / 128; i++) {
            int idx = tid + i * 128;          // over KC*TN/4
            int kk  = idx / (TN / 4);
            int n4  = (idx % (TN / 4)) * 4;
            float4 v = *(const float4*)&W[(kc + kk) * TN + n4];
            wt[(n4 + 0) * PAD + kk] = f2tf(v.x);
            wt[(n4 + 1) * PAD + kk] = f2tf(v.y);
            wt[(n4 + 2) * PAD + kk] = f2tf(v.z);
            wt[(n4 + 3) * PAD + kk] = f2tf(v.w);
        }
        __syncthreads();

#pragma unroll
        for (int k0 = 0; k0 < KC; k0 += 8) {
            unsigned a0 = xs[(mw + r4    ) * PAD + k0 + c4    ];
            unsigned a1 = xs[(mw + r4 + 8) * PAD + k0 + c4    ];
            unsigned a2 = xs[(mw + r4    ) * PAD + k0 + c4 + 4];
            unsigned a3 = xs[(mw + r4 + 8) * PAD + k0 + c4 + 4];
#pragma unroll
            for (int nt = 0; nt < NT; nt++) {
                unsigned b0 = wt[(nt * 8 + r4) * PAD + k0 + c4    ];
                unsigned b1 = wt[(nt * 8 + r4) * PAD + k0 + c4 + 4];
                asm volatile(
                    "mma.sync.aligned.m16n8k8.row.col.f32.tf32.tf32.f32 "
                    "{%0,%1,%2,%3}, {%4,%5,%6,%7}, {%8,%9}, {%0,%1,%2,%3};"
                    : "+f"(acc[nt][0]), "+f"(acc[nt][1]),
                      "+f"(acc[nt][2]), "+f"(acc[nt][3])
                    : "r"(a0), "r"(a1), "r"(a2), "r"(a3), "r"(b0), "r"(b1));
            }
        }
        __syncthreads();
    }

    // epilogue: d0,d1 -> [row][col,col+1]; d2,d3 -> [row+8][col,col+1]
    const int colb = c4 * 2;
    const int rowa = m0 + mw + r4;
#pragma unroll
    for (int nt = 0; nt < NT; nt++) {
        int n0 = nt * 8 + colb;
        if (rowa < M)
            *(float2*)&Y[rowa * TN + n0] = make_float2(acc[nt][0], acc[nt][1]);
        if (rowa + 8 < M)
            *(float2*)&Y[(rowa + 8) * TN + n0] = make_float2(acc[nt][2], acc[nt][3]);
    }
}

// ---------------------------------------------------------------------------
// Pull aggregation, one warp per node.
// ---------------------------------------------------------------------------
__global__ void k_gather128(int M)
{
    int w    = (blockIdx.x * blockDim.x + threadIdx.x) >> 5;
    int lane = threadIdx.x & 31;
    if (w >= M) return;
    const float4* __restrict__ H = (const float4*)g_h1;
    int beg = g_ptr[w], end = g_ptr[w + 1];
    float cs = g_dinv[w]; cs *= cs;
    float4 v = H[w * 32 + lane];
    float4 a0 = make_float4(v.x * cs, v.y * cs, v.z * cs, v.w * cs);
    float4 a1 = make_float4(0.f, 0.f, 0.f, 0.f);
    int e = beg;
    for (; e + 1 < end; e += 2) {
        int2 p0 = g_edge[e];
        int2 p1 = g_edge[e + 1];
        float c0 = __int_as_float(p0.y);
        float c1 = __int_as_float(p1.y);
        float4 v0 = H[p0.x * 32 + lane];
        float4 v1 = H[p1.x * 32 + lane];
        a0.x = fmaf(v0.x, c0, a0.x); a0.y = fmaf(v0.y, c0, a0.y);
        a0.z = fmaf(v0.z, c0, a0.z); a0.w = fmaf(v0.w, c0, a0.w);
        a1.x = fmaf(v1.x, c1, a1.x); a1.y = fmaf(v1.y, c1, a1.y);
        a1.z = fmaf(v1.z, c1, a1.z); a1.w = fmaf(v1.w, c1, a1.w);
    }
    if (e < end) {
        int2 p0 = g_edge[e];
        float c0 = __int_as_float(p0.y);
        float4 v0 = H[p0.x * 32 + lane];
        a0.x = fmaf(v0.x, c0, a0.x); a0.y = fmaf(v0.y, c0, a0.y);
        a0.z = fmaf(v0.z, c0, a0.z); a0.w = fmaf(v0.w, c0, a0.w);
    }
    a0.x += a1.x; a0.y += a1.y; a0.z += a1.z; a0.w += a1.w;
    ((float4*)g_agg1)[w * 32 + lane] = a0;
}

__global__ void k_gather64(const float* __restrict__ b2, float* __restrict__ outp, int M)
{
    int w    = (blockIdx.x * blockDim.x + threadIdx.x) >> 5;
    int lane = threadIdx.x & 31;
    if (w >= M) return;
    const float2* __restrict__ H = (const float2*)g_h2;
    int beg = g_ptr[w], end = g_ptr[w + 1];
    float cs = g_dinv[w]; cs *= cs;
    float2 v = H[w * 32 + lane];
    float2 bb = ((const float2*)b2)[lane];
    float2 a0 = make_float2(fmaf(v.x, cs, bb.x), fmaf(v.y, cs, bb.y));
    float2 a1 = make_float2(0.f, 0.f);
    int e = beg;
    for (; e + 1 < end; e += 2) {
        int2 p0 = g_edge[e];
        int2 p1 = g_edge[e + 1];
        float c0 = __int_as_float(p0.y);
        float c1 = __int_as_float(p1.y);
        float2 v0 = H[p0.x * 32 + lane];
        float2 v1 = H[p1.x * 32 + lane];
        a0.x = fmaf(v0.x, c0, a0.x); a0.y = fmaf(v0.y, c0, a0.y);
        a1.x = fmaf(v1.x, c1, a1.x); a1.y = fmaf(v1.y, c1, a1.y);
    }
    if (e < end) {
        int2 p0 = g_edge[e];
        float c0 = __int_as_float(p0.y);
        float2 v0 = H[p0.x * 32 + lane];
        a0.x = fmaf(v0.x, c0, a0.x); a0.y = fmaf(v0.y, c0, a0.y);
    }
    a0.x += a1.x; a0.y += a1.y;
    ((float2*)outp)[w * 32 + lane] = a0;
}

// ---------------------------------------------------------------------------
extern "C" void kernel_launch(void* const* d_in, const int* in_sizes, int n_in,
                              void* d_out, int out_size)
{
    const float* x  = (const float*)d_in[0];
    const void*  ei = d_in[1];
    const float* W1 = (const float*)d_in[2];
    const float* b1 = (const float*)d_in[3];
    const float* W2 = (const float*)d_in[4];
    const float* b2 = (const float*)d_in[5];
    float*       out = (float*)d_out;

    const int M = in_sizes[0] / INF;   // 50000
    const int E = in_sizes[1] / 2;     // 800000

    const int T = 256;

    // 0. dtype probe + decode + degree histogram
    k_probe       <<<1, 256>>>((const int*)ei, in_sizes[1]);
    k_zero_cnt    <<<(M + T - 1) / T, T>>>(M);
    k_decode_count<<<(E + T - 1) / T, T>>>(ei, E);

    // 1. scan (+dinv) + CSR fill
    k_scan   <<<1, 1024>>>(M);
    k_fillcsr<<<(E + T - 1) / T, T>>>(E);

    // 2. layer 1: h1 = X @ W1 (tf32 MMA) ; pull-aggregate into agg1
    k_gemm_tf32<128, false><<<(M + 63) / 64, 128>>>(x, W1, b1, M);
    k_gather128<<<(M * 32 + T - 1) / T, T>>>(M);

    // 3. layer 2: h2 = relu(agg1 + b1) @ W2 (tf32 MMA) ; aggregate + bias -> out
    k_gemm_tf32<64, true><<<(M + 63) / 64, 128>>>(nullptr, W2, b1, M);
    k_gather64<<<(M * 32 + T - 1) / T, T>>>(b2, out, M);
}

// round 6
// speedup vs baseline: 1.5964x; 1.5964x over previous
#include <cuda_runtime.h>
#include <cuda_bf16.h>

// ---------------------------------------------------------------------------
// 2-layer GCN, pull aggregation via on-device CSR, tf32 tensor-core GEMMs,
// fully parallel 3-phase prefix scan for the CSR build.
// ---------------------------------------------------------------------------

#define NMAX   50048
#define EMAX   800000
#define INF    128
#define OUTF   64
#define SCB    512                    // scan block size (nodes per block)
#define NSB    ((NMAX + SCB - 1) / SCB)

__device__ int   g_is64;
__device__ int   g_src [EMAX];
__device__ int   g_dst [EMAX];
__device__ int   g_cnt [NMAX];        // in-degree (without self loop)
__device__ int   g_ptr [NMAX + 1];    // CSR row pointers
__device__ int   g_fill[NMAX];        // fill cursors
__device__ int   g_bsum[128];         // per-block sums
__device__ int   g_boff[128];         // per-block exclusive offsets
__device__ int2  g_edge[EMAX];        // packed (src, __float_as_int(coeff))
__device__ float g_dinv[NMAX];
__device__ float g_h1  [NMAX * INF];  // X @ W1
__device__ float g_agg1[NMAX * INF];  // aggregated layer-1 (pre bias/relu)
__device__ float g_h2  [NMAX * OUTF]; // relu(agg1+b1) @ W2

// ---------------------------------------------------------------------------
__global__ void k_probe(const int* __restrict__ w32, int words) {
    __shared__ int viol;
    if (threadIdx.x == 0) viol = 0;
    __syncthreads();
    int nchk = words / 2;
    if (nchk > 32768) nchk = 32768;
    int bad = 0;
    for (int i = threadIdx.x; i < nchk; i += blockDim.x)
        if (w32[2 * i + 1] != 0) bad = 1;
    if (bad) atomicOr(&viol, 1);
    __syncthreads();
    if (threadIdx.x == 0) g_is64 = (viol == 0) ? 1 : 0;
}

__global__ void k_zero_cnt(int n) {
    int i = blockIdx.x * blockDim.x + threadIdx.x;
    if (i < n) g_cnt[i] = 0;
}

__global__ void k_decode_count(const void* __restrict__ ei, int E) {
    int e = blockIdx.x * blockDim.x + threadIdx.x;
    if (e >= E) return;
    int s, d;
    if (g_is64) {
        const long long* p = (const long long*)ei;
        s = (int)p[e];  d = (int)p[E + e];
    } else {
        const int* p = (const int*)ei;
        s = p[e];       d = p[E + e];
    }
    g_src[e] = s;
    g_dst[e] = d;
    atomicAdd(&g_cnt[d], 1);
}

// ---------------------------------------------------------------------------
// 3-phase parallel exclusive scan of g_cnt -> g_ptr/g_fill  (+ dinv in phase 1)
// ---------------------------------------------------------------------------
__global__ void k_blocksum(int M) {
    __shared__ int ws[16];
    int t    = threadIdx.x;
    int node = blockIdx.x * SCB + t;
    int c = (node < M) ? g_cnt[node] : 0;
    if (node < M) g_dinv[node] = rsqrtf((float)(c + 1));   // +1 self loop
    int v = c;
#pragma unroll
    for (int o = 16; o; o >>= 1) v += __shfl_down_sync(0xffffffffu, v, o);
    if ((t & 31) == 0) ws[t >> 5] = v;
    __syncthreads();
    if (t < 16) {
        int u = ws[t];
#pragma unroll
        for (int o = 8; o; o >>= 1) u += __shfl_down_sync(0xffffu, u, o);
        if (t == 0) g_bsum[blockIdx.x] = u;
    }
}

__global__ void k_scanb(int nb, int M) {
    __shared__ int sh[128];
    int t = threadIdx.x;
    int v = (t < nb) ? g_bsum[t] : 0;
    sh[t] = v;
    __syncthreads();
    for (int o = 1; o < 128; o <<= 1) {
        int u = (t >= o) ? sh[t - o] : 0;
        __syncthreads();
        sh[t] += u;
        __syncthreads();
    }
    if (t < nb) g_boff[t] = sh[t] - v;
    if (t == nb - 1) g_ptr[M] = sh[t];
}

__global__ void k_scanc(int M) {
    __shared__ int sh[SCB];
    int t    = threadIdx.x;
    int node = blockIdx.x * SCB + t;
    int c = (node < M) ? g_cnt[node] : 0;
    sh[t] = c;
    __syncthreads();
    for (int o = 1; o < SCB; o <<= 1) {
        int u = (t >= o) ? sh[t - o] : 0;
        __syncthreads();
        sh[t] += u;
        __syncthreads();
    }
    if (node < M) {
        int excl = sh[t] - c + g_boff[blockIdx.x];
        g_ptr[node]  = excl;
        g_fill[node] = excl;
    }
}

__global__ void k_fillcsr(int E) {
    int e = blockIdx.x * blockDim.x + threadIdx.x;
    if (e >= E) return;
    int s = g_src[e];
    int d = g_dst[e];
    float c = g_dinv[s] * g_dinv[d];
    int pos = atomicAdd(&g_fill[d], 1);
    g_edge[pos] = make_int2(s, __float_as_int(c));
}

// ---------------------------------------------------------------------------
// tf32 tensor-core GEMM:  Y[M,TN] = op(X)[M,128] * W[128,TN]
// ---------------------------------------------------------------------------
__device__ __forceinline__ unsigned f2tf(float f) {
    unsigned r;
    asm("cvt.rna.tf32.f32 %0, %1;" : "=r"(r) : "f"(f));
    return r;
}

template <int TN, bool PRELU>
__global__ void k_gemm_tf32(const float* __restrict__ Xin, const float* __restrict__ W,
                            const float* __restrict__ bias_in, int M)
{
    constexpr int KC  = 32;
    constexpr int NT  = TN / 8;
    constexpr int PAD = 36;

    const float* __restrict__ X = PRELU ? (const float*)g_agg1 : Xin;
    float* __restrict__ Y       = PRELU ? g_h2 : g_h1;

    __shared__ unsigned xs[64 * PAD];
    __shared__ unsigned wt[TN * PAD];

    const int tid  = threadIdx.x;
    const int lane = tid & 31;
    const int wid  = tid >> 5;
    const int m0   = blockIdx.x * 64;
    const int mw   = wid * 16;

    float acc[NT][4];
#pragma unroll
    for (int t = 0; t < NT; t++) { acc[t][0]=acc[t][1]=acc[t][2]=acc[t][3]=0.f; }

    const int r4 = lane >> 2;
    const int c4 = lane & 3;

    for (int kc = 0; kc < 128; kc += KC) {
#pragma unroll
        for (int i = 0; i < 4; i++) {
            int idx = tid + i * 128;
            int r   = idx >> 3;
            int kv  = (idx & 7) * 4;
            int row = m0 + r;
            float4 v = make_float4(0.f, 0.f, 0.f, 0.f);
            if (row < M) v = *(const float4*)&X[row * 128 + kc + kv];
            if (PRELU) {
                float4 b = *(const float4*)&bias_in[kc + kv];
                v.x = fmaxf(v.x + b.x, 0.f);
                v.y = fmaxf(v.y + b.y, 0.f);
                v.z = fmaxf(v.z + b.z, 0.f);
                v.w = fmaxf(v.w + b.w, 0.f);
            }
            uint4 u = make_uint4(f2tf(v.x), f2tf(v.y), f2tf(v.z), f2tf(v.w));
            *(uint4*)&xs[r * PAD + kv] = u;
        }
#pragma unroll
        for (int i = 0; i < (KC * TN / 4) / 128; i++) {
            int idx = tid + i * 128;
            int kk  = idx / (TN / 4);
            int n4  = (idx % (TN / 4)) * 4;
            float4 v = *(const float4*)&W[(kc + kk) * TN + n4];
            wt[(n4 + 0) * PAD + kk] = f2tf(v.x);
            wt[(n4 + 1) * PAD + kk] = f2tf(v.y);
            wt[(n4 + 2) * PAD + kk] = f2tf(v.z);
            wt[(n4 + 3) * PAD + kk] = f2tf(v.w);
        }
        __syncthreads();

#pragma unroll
        for (int k0 = 0; k0 < KC; k0 += 8) {
            unsigned a0 = xs[(mw + r4    ) * PAD + k0 + c4    ];
            unsigned a1 = xs[(mw + r4 + 8) * PAD + k0 + c4    ];
            unsigned a2 = xs[(mw + r4    ) * PAD + k0 + c4 + 4];
            unsigned a3 = xs[(mw + r4 + 8) * PAD + k0 + c4 + 4];
#pragma unroll
            for (int nt = 0; nt < NT; nt++) {
                unsigned b0 = wt[(nt * 8 + r4) * PAD + k0 + c4    ];
                unsigned b1 = wt[(nt * 8 + r4) * PAD + k0 + c4 + 4];
                asm volatile(
                    "mma.sync.aligned.m16n8k8.row.col.f32.tf32.tf32.f32 "
                    "{%0,%1,%2,%3}, {%4,%5,%6,%7}, {%8,%9}, {%0,%1,%2,%3};"
                    : "+f"(acc[nt][0]), "+f"(acc[nt][1]),
                      "+f"(acc[nt][2]), "+f"(acc[nt][3])
                    : "r"(a0), "r"(a1), "r"(a2), "r"(a3), "r"(b0), "r"(b1));
            }
        }
        __syncthreads();
    }

    const int colb = c4 * 2;
    const int rowa = m0 + mw + r4;
#pragma unroll
    for (int nt = 0; nt < NT; nt++) {
        int n0 = nt * 8 + colb;
        if (rowa < M)
            *(float2*)&Y[rowa * TN + n0] = make_float2(acc[nt][0], acc[nt][1]);
        if (rowa + 8 < M)
            *(float2*)&Y[(rowa + 8) * TN + n0] = make_float2(acc[nt][2], acc[nt][3]);
    }
}

// ---------------------------------------------------------------------------
// Pull aggregation, one warp per node.
// ---------------------------------------------------------------------------
__global__ void k_gather128(int M)
{
    int w    = (blockIdx.x * blockDim.x + threadIdx.x) >> 5;
    int lane = threadIdx.x & 31;
    if (w >= M) return;
    const float4* __restrict__ H = (const float4*)g_h1;
    int beg = g_ptr[w], end = g_ptr[w + 1];
    float cs = g_dinv[w]; cs *= cs;
    float4 v = H[w * 32 + lane];
    float4 a0 = make_float4(v.x * cs, v.y * cs, v.z * cs, v.w * cs);
    float4 a1 = make_float4(0.f, 0.f, 0.f, 0.f);
    int e = beg;
    for (; e + 1 < end; e += 2) {
        int2 p0 = g_edge[e];
        int2 p1 = g_edge[e + 1];
        float c0 = __int_as_float(p0.y);
        float c1 = __int_as_float(p1.y);
        float4 v0 = H[p0.x * 32 + lane];
        float4 v1 = H[p1.x * 32 + lane];
        a0.x = fmaf(v0.x, c0, a0.x); a0.y = fmaf(v0.y, c0, a0.y);
        a0.z = fmaf(v0.z, c0, a0.z); a0.w = fmaf(v0.w, c0, a0.w);
        a1.x = fmaf(v1.x, c1, a1.x); a1.y = fmaf(v1.y, c1, a1.y);
        a1.z = fmaf(v1.z, c1, a1.z); a1.w = fmaf(v1.w, c1, a1.w);
    }
    if (e < end) {
        int2 p0 = g_edge[e];
        float c0 = __int_as_float(p0.y);
        float4 v0 = H[p0.x * 32 + lane];
        a0.x = fmaf(v0.x, c0, a0.x); a0.y = fmaf(v0.y, c0, a0.y);
        a0.z = fmaf(v0.z, c0, a0.z); a0.w = fmaf(v0.w, c0, a0.w);
    }
    a0.x += a1.x; a0.y += a1.y; a0.z += a1.z; a0.w += a1.w;
    ((float4*)g_agg1)[w * 32 + lane] = a0;
}

__global__ void k_gather64(const float* __restrict__ b2, float* __restrict__ outp, int M)
{
    int w    = (blockIdx.x * blockDim.x + threadIdx.x) >> 5;
    int lane = threadIdx.x & 31;
    if (w >= M) return;
    const float2* __restrict__ H = (const float2*)g_h2;
    int beg = g_ptr[w], end = g_ptr[w + 1];
    float cs = g_dinv[w]; cs *= cs;
    float2 v = H[w * 32 + lane];
    float2 bb = ((const float2*)b2)[lane];
    float2 a0 = make_float2(fmaf(v.x, cs, bb.x), fmaf(v.y, cs, bb.y));
    float2 a1 = make_float2(0.f, 0.f);
    int e = beg;
    for (; e + 1 < end; e += 2) {
        int2 p0 = g_edge[e];
        int2 p1 = g_edge[e + 1];
        float c0 = __int_as_float(p0.y);
        float c1 = __int_as_float(p1.y);
        float2 v0 = H[p0.x * 32 + lane];
        float2 v1 = H[p1.x * 32 + lane];
        a0.x = fmaf(v0.x, c0, a0.x); a0.y = fmaf(v0.y, c0, a0.y);
        a1.x = fmaf(v1.x, c1, a1.x); a1.y = fmaf(v1.y, c1, a1.y);
    }
    if (e < end) {
        int2 p0 = g_edge[e];
        float c0 = __int_as_float(p0.y);
        float2 v0 = H[p0.x * 32 + lane];
        a0.x = fmaf(v0.x, c0, a0.x); a0.y = fmaf(v0.y, c0, a0.y);
    }
    a0.x += a1.x; a0.y += a1.y;
    ((float2*)outp)[w * 32 + lane] = a0;
}

// ---------------------------------------------------------------------------
extern "C" void kernel_launch(void* const* d_in, const int* in_sizes, int n_in,
                              void* d_out, int out_size)
{
    const float* x  = (const float*)d_in[0];
    const void*  ei = d_in[1];
    const float* W1 = (const float*)d_in[2];
    const float* b1 = (const float*)d_in[3];
    const float* W2 = (const float*)d_in[4];
    const float* b2 = (const float*)d_in[5];
    float*       out = (float*)d_out;

    const int M = in_sizes[0] / INF;   // 50000
    const int E = in_sizes[1] / 2;     // 800000

    const int T  = 256;
    const int NB = (M + SCB - 1) / SCB;

    // 0. dtype probe + decode + degree histogram
    k_probe       <<<1, 256>>>((const int*)ei, in_sizes[1]);
    k_zero_cnt    <<<(M + T - 1) / T, T>>>(M);
    k_decode_count<<<(E + T - 1) / T, T>>>(ei, E);

    // 1. parallel scan (+dinv) + CSR fill
    k_blocksum<<<NB, SCB>>>(M);
    k_scanb   <<<1, 128>>>(NB, M);
    k_scanc   <<<NB, SCB>>>(M);
    k_fillcsr <<<(E + T - 1) / T, T>>>(E);

    // 2. layer 1: h1 = X @ W1 (tf32 MMA) ; pull-aggregate into agg1
    k_gemm_tf32<128, false><<<(M + 63) / 64, 128>>>(x, W1, b1, M);
    k_gather128<<<(M * 32 + T - 1) / T, T>>>(M);

    // 3. layer 2: h2 = relu(agg1 + b1) @ W2 (tf32 MMA) ; aggregate + bias -> out
    k_gemm_tf32<64, true><<<(M + 63) / 64, 128>>>(nullptr, W2, b1, M);
    k_gather64<<<(M * 32 + T - 1) / T, T>>>(b2, out, M);
}

// round 7
// speedup vs baseline: 1.7950x; 1.1244x over previous
#include <cuda_runtime.h>
#include <cuda_bf16.h>

// ---------------------------------------------------------------------------
// 2-layer GCN. Pull aggregation via on-device CSR, tf32 tensor-core GEMMs,
// parallel 3-phase scan. CSR-build chain overlapped with GEMM1 on a forked
// stream (event fork/join — graph-capture legal).
// ---------------------------------------------------------------------------

#define NMAX   50048
#define EMAX   800000
#define INF    128
#define OUTF   64
#define SCB    512

__device__ int   g_is64;
__device__ int   g_cnt [NMAX];        // in-degree (without self loop)
__device__ int   g_ptr [NMAX + 1];    // CSR row pointers
__device__ int   g_fill[NMAX];        // fill cursors
__device__ int   g_bsum[128];
__device__ int   g_boff[128];
__device__ int2  g_edge[EMAX];        // packed (src, __float_as_int(coeff))
__device__ float g_dinv[NMAX];
__device__ float g_h1  [NMAX * INF];
__device__ float g_agg1[NMAX * INF];
__device__ float g_h2  [NMAX * OUTF];

// ---------------------------------------------------------------------------
__global__ void k_probe(const int* __restrict__ w32, int words) {
    __shared__ int viol;
    if (threadIdx.x == 0) viol = 0;
    __syncthreads();
    int nchk = words / 2;
    if (nchk > 32768) nchk = 32768;
    int bad = 0;
    for (int i = threadIdx.x; i < nchk; i += blockDim.x)
        if (w32[2 * i + 1] != 0) bad = 1;
    if (bad) atomicOr(&viol, 1);
    __syncthreads();
    if (threadIdx.x == 0) g_is64 = (viol == 0) ? 1 : 0;
}

__global__ void k_zero_cnt(int n) {
    int i = blockIdx.x * blockDim.x + threadIdx.x;
    if (i < n) g_cnt[i] = 0;
}

// histogram of destinations (reads only dst half of edge_index)
__global__ void k_count(const void* __restrict__ ei, int E) {
    int e = blockIdx.x * blockDim.x + threadIdx.x;
    if (e >= E) return;
    int d = g_is64 ? (int)((const long long*)ei)[E + e]
                   : ((const int*)ei)[E + e];
    atomicAdd(&g_cnt[d], 1);
}

// ---------------------------------------------------------------------------
// 3-phase parallel exclusive scan of g_cnt -> g_ptr/g_fill  (+ dinv)
// ---------------------------------------------------------------------------
__global__ void k_blocksum(int M) {
    __shared__ int ws[16];
    int t    = threadIdx.x;
    int node = blockIdx.x * SCB + t;
    int c = (node < M) ? g_cnt[node] : 0;
    if (node < M) g_dinv[node] = rsqrtf((float)(c + 1));
    int v = c;
#pragma unroll
    for (int o = 16; o; o >>= 1) v += __shfl_down_sync(0xffffffffu, v, o);
    if ((t & 31) == 0) ws[t >> 5] = v;
    __syncthreads();
    if (t < 16) {
        int u = ws[t];
#pragma unroll
        for (int o = 8; o; o >>= 1) u += __shfl_down_sync(0xffffu, u, o);
        if (t == 0) g_bsum[blockIdx.x] = u;
    }
}

__global__ void k_scanb(int nb, int M) {
    __shared__ int sh[128];
    int t = threadIdx.x;
    int v = (t < nb) ? g_bsum[t] : 0;
    sh[t] = v;
    __syncthreads();
    for (int o = 1; o < 128; o <<= 1) {
        int u = (t >= o) ? sh[t - o] : 0;
        __syncthreads();
        sh[t] += u;
        __syncthreads();
    }
    if (t < nb) g_boff[t] = sh[t] - v;
    if (t == nb - 1) g_ptr[M] = sh[t];
}

__global__ void k_scanc(int M) {
    __shared__ int sh[SCB];
    int t    = threadIdx.x;
    int node = blockIdx.x * SCB + t;
    int c = (node < M) ? g_cnt[node] : 0;
    sh[t] = c;
    __syncthreads();
    for (int o = 1; o < SCB; o <<= 1) {
        int u = (t >= o) ? sh[t - o] : 0;
        __syncthreads();
        sh[t] += u;
        __syncthreads();
    }
    if (node < M) {
        int excl = sh[t] - c + g_boff[blockIdx.x];
        g_ptr[node]  = excl;
        g_fill[node] = excl;
    }
}

// fill CSR reading edge_index directly (no staging arrays)
__global__ void k_fillcsr(const void* __restrict__ ei, int E) {
    int e = blockIdx.x * blockDim.x + threadIdx.x;
    if (e >= E) return;
    int s, d;
    if (g_is64) {
        const long long* p = (const long long*)ei;
        s = (int)p[e];  d = (int)p[E + e];
    } else {
        const int* p = (const int*)ei;
        s = p[e];       d = p[E + e];
    }
    float c = g_dinv[s] * g_dinv[d];
    int pos = atomicAdd(&g_fill[d], 1);
    g_edge[pos] = make_int2(s, __float_as_int(c));
}

// ---------------------------------------------------------------------------
// tf32 tensor-core GEMM:  Y[M,TN] = op(X)[M,128] * W[128,TN]
// ---------------------------------------------------------------------------
__device__ __forceinline__ unsigned f2tf(float f) {
    unsigned r;
    asm("cvt.rna.tf32.f32 %0, %1;" : "=r"(r) : "f"(f));
    return r;
}

template <int TN, bool PRELU>
__global__ void k_gemm_tf32(const float* __restrict__ Xin, const float* __restrict__ W,
                            const float* __restrict__ bias_in, int M)
{
    constexpr int KC  = 32;
    constexpr int NT  = TN / 8;
    constexpr int PAD = 36;

    const float* __restrict__ X = PRELU ? (const float*)g_agg1 : Xin;
    float* __restrict__ Y       = PRELU ? g_h2 : g_h1;

    __shared__ unsigned xs[64 * PAD];
    __shared__ unsigned wt[TN * PAD];

    const int tid  = threadIdx.x;
    const int lane = tid & 31;
    const int wid  = tid >> 5;
    const int m0   = blockIdx.x * 64;
    const int mw   = wid * 16;

    float acc[NT][4];
#pragma unroll
    for (int t = 0; t < NT; t++) { acc[t][0]=acc[t][1]=acc[t][2]=acc[t][3]=0.f; }

    const int r4 = lane >> 2;
    const int c4 = lane & 3;

    for (int kc = 0; kc < 128; kc += KC) {
#pragma unroll
        for (int i = 0; i < 4; i++) {
            int idx = tid + i * 128;
            int r   = idx >> 3;
            int kv  = (idx & 7) * 4;
            int row = m0 + r;
            float4 v = make_float4(0.f, 0.f, 0.f, 0.f);
            if (row < M) v = *(const float4*)&X[row * 128 + kc + kv];
            if (PRELU) {
                float4 b = *(const float4*)&bias_in[kc + kv];
                v.x = fmaxf(v.x + b.x, 0.f);
                v.y = fmaxf(v.y + b.y, 0.f);
                v.z = fmaxf(v.z + b.z, 0.f);
                v.w = fmaxf(v.w + b.w, 0.f);
            }
            uint4 u = make_uint4(f2tf(v.x), f2tf(v.y), f2tf(v.z), f2tf(v.w));
            *(uint4*)&xs[r * PAD + kv] = u;
        }
#pragma unroll
        for (int i = 0; i < (KC * TN / 4) / 128; i++) {
            int idx = tid + i * 128;
            int kk  = idx / (TN / 4);
            int n4  = (idx % (TN / 4)) * 4;
            float4 v = *(const float4*)&W[(kc + kk) * TN + n4];
            wt[(n4 + 0) * PAD + kk] = f2tf(v.x);
            wt[(n4 + 1) * PAD + kk] = f2tf(v.y);
            wt[(n4 + 2) * PAD + kk] = f2tf(v.z);
            wt[(n4 + 3) * PAD + kk] = f2tf(v.w);
        }
        __syncthreads();

#pragma unroll
        for (int k0 = 0; k0 < KC; k0 += 8) {
            unsigned a0 = xs[(mw + r4    ) * PAD + k0 + c4    ];
            unsigned a1 = xs[(mw + r4 + 8) * PAD + k0 + c4    ];
            unsigned a2 = xs[(mw + r4    ) * PAD + k0 + c4 + 4];
            unsigned a3 = xs[(mw + r4 + 8) * PAD + k0 + c4 + 4];
#pragma unroll
            for (int nt = 0; nt < NT; nt++) {
                unsigned b0 = wt[(nt * 8 + r4) * PAD + k0 + c4    ];
                unsigned b1 = wt[(nt * 8 + r4) * PAD + k0 + c4 + 4];
                asm volatile(
                    "mma.sync.aligned.m16n8k8.row.col.f32.tf32.tf32.f32 "
                    "{%0,%1,%2,%3}, {%4,%5,%6,%7}, {%8,%9}, {%0,%1,%2,%3};"
                    : "+f"(acc[nt][0]), "+f"(acc[nt][1]),
                      "+f"(acc[nt][2]), "+f"(acc[nt][3])
                    : "r"(a0), "r"(a1), "r"(a2), "r"(a3), "r"(b0), "r"(b1));
            }
        }
        __syncthreads();
    }

    const int colb = c4 * 2;
    const int rowa = m0 + mw + r4;
#pragma unroll
    for (int nt = 0; nt < NT; nt++) {
        int n0 = nt * 8 + colb;
        if (rowa < M)
            *(float2*)&Y[rowa * TN + n0] = make_float2(acc[nt][0], acc[nt][1]);
        if (rowa + 8 < M)
            *(float2*)&Y[(rowa + 8) * TN + n0] = make_float2(acc[nt][2], acc[nt][3]);
    }
}

// ---------------------------------------------------------------------------
// Pull aggregation, one warp per node.
// ---------------------------------------------------------------------------
__global__ void k_gather128(int M)
{
    int w    = (blockIdx.x * blockDim.x + threadIdx.x) >> 5;
    int lane = threadIdx.x & 31;
    if (w >= M) return;
    const float4* __restrict__ H = (const float4*)g_h1;
    int beg = g_ptr[w], end = g_ptr[w + 1];
    float cs = g_dinv[w]; cs *= cs;
    float4 v = H[w * 32 + lane];
    float4 a0 = make_float4(v.x * cs, v.y * cs, v.z * cs, v.w * cs);
    float4 a1 = make_float4(0.f, 0.f, 0.f, 0.f);
    int e = beg;
    for (; e + 1 < end; e += 2) {
        int2 p0 = g_edge[e];
        int2 p1 = g_edge[e + 1];
        float c0 = __int_as_float(p0.y);
        float c1 = __int_as_float(p1.y);
        float4 v0 = H[p0.x * 32 + lane];
        float4 v1 = H[p1.x * 32 + lane];
        a0.x = fmaf(v0.x, c0, a0.x); a0.y = fmaf(v0.y, c0, a0.y);
        a0.z = fmaf(v0.z, c0, a0.z); a0.w = fmaf(v0.w, c0, a0.w);
        a1.x = fmaf(v1.x, c1, a1.x); a1.y = fmaf(v1.y, c1, a1.y);
        a1.z = fmaf(v1.z, c1, a1.z); a1.w = fmaf(v1.w, c1, a1.w);
    }
    if (e < end) {
        int2 p0 = g_edge[e];
        float c0 = __int_as_float(p0.y);
        float4 v0 = H[p0.x * 32 + lane];
        a0.x = fmaf(v0.x, c0, a0.x); a0.y = fmaf(v0.y, c0, a0.y);
        a0.z = fmaf(v0.z, c0, a0.z); a0.w = fmaf(v0.w, c0, a0.w);
    }
    a0.x += a1.x; a0.y += a1.y; a0.z += a1.z; a0.w += a1.w;
    ((float4*)g_agg1)[w * 32 + lane] = a0;
}

__global__ void k_gather64(const float* __restrict__ b2, float* __restrict__ outp, int M)
{
    int w    = (blockIdx.x * blockDim.x + threadIdx.x) >> 5;
    int lane = threadIdx.x & 31;
    if (w >= M) return;
    const float2* __restrict__ H = (const float2*)g_h2;
    int beg = g_ptr[w], end = g_ptr[w + 1];
    float cs = g_dinv[w]; cs *= cs;
    float2 v = H[w * 32 + lane];
    float2 bb = ((const float2*)b2)[lane];
    float2 a0 = make_float2(fmaf(v.x, cs, bb.x), fmaf(v.y, cs, bb.y));
    float2 a1 = make_float2(0.f, 0.f);
    int e = beg;
    for (; e + 1 < end; e += 2) {
        int2 p0 = g_edge[e];
        int2 p1 = g_edge[e + 1];
        float c0 = __int_as_float(p0.y);
        float c1 = __int_as_float(p1.y);
        float2 v0 = H[p0.x * 32 + lane];
        float2 v1 = H[p1.x * 32 + lane];
        a0.x = fmaf(v0.x, c0, a0.x); a0.y = fmaf(v0.y, c0, a0.y);
        a1.x = fmaf(v1.x, c1, a1.x); a1.y = fmaf(v1.y, c1, a1.y);
    }
    if (e < end) {
        int2 p0 = g_edge[e];
        float c0 = __int_as_float(p0.y);
        float2 v0 = H[p0.x * 32 + lane];
        a0.x = fmaf(v0.x, c0, a0.x); a0.y = fmaf(v0.y, c0, a0.y);
    }
    a0.x += a1.x; a0.y += a1.y;
    ((float2*)outp)[w * 32 + lane] = a0;
}

// ---------------------------------------------------------------------------
extern "C" void kernel_launch(void* const* d_in, const int* in_sizes, int n_in,
                              void* d_out, int out_size)
{
    const float* x  = (const float*)d_in[0];
    const void*  ei = d_in[1];
    const float* W1 = (const float*)d_in[2];
    const float* b1 = (const float*)d_in[3];
    const float* W2 = (const float*)d_in[4];
    const float* b2 = (const float*)d_in[5];
    float*       out = (float*)d_out;

    const int M = in_sizes[0] / INF;   // 50000
    const int E = in_sizes[1] / 2;     // 800000

    const int T  = 256;
    const int NB = (M + SCB - 1) / SCB;

    // fork a side stream for the CSR-build chain (independent of GEMM1)
    cudaStream_t s1;
    cudaStreamCreateWithFlags(&s1, cudaStreamNonBlocking);
    cudaEvent_t evFork, evJoin;
    cudaEventCreateWithFlags(&evFork, cudaEventDisableTiming);
    cudaEventCreateWithFlags(&evJoin, cudaEventDisableTiming);

    cudaEventRecord(evFork, 0);
    cudaStreamWaitEvent(s1, evFork, 0);

    // --- chain B (s1): CSR build ---
    k_probe   <<<1, 256, 0, s1>>>((const int*)ei, in_sizes[1]);
    k_zero_cnt<<<(M + T - 1) / T, T, 0, s1>>>(M);
    k_count   <<<(E + T - 1) / T, T, 0, s1>>>(ei, E);
    k_blocksum<<<NB, SCB, 0, s1>>>(M);
    k_scanb   <<<1, 128, 0, s1>>>(NB, M);
    k_scanc   <<<NB, SCB, 0, s1>>>(M);
    k_fillcsr <<<(E + T - 1) / T, T, 0, s1>>>(ei, E);
    cudaEventRecord(evJoin, s1);

    // --- chain A (default stream): layer-1 GEMM ---
    k_gemm_tf32<128, false><<<(M + 63) / 64, 128>>>(x, W1, b1, M);

    // join, then the dependent tail
    cudaStreamWaitEvent(0, evJoin, 0);
    k_gather128<<<(M * 32 + T - 1) / T, T>>>(M);
    k_gemm_tf32<64, true><<<(M + 63) / 64, 128>>>(nullptr, W2, b1, M);
    k_gather64<<<(M * 32 + T - 1) / T, T>>>(b2, out, M);
}